// round 2
// baseline (speedup 1.0000x reference)
#include <cuda_runtime.h>
#include <math.h>

#define N_NODES 4096
#define IN_F    512
#define NHEAD   8
#define DHEAD   64
#define CTOT    (NHEAD * DHEAD)   // 512

// Scratch (static device globals — no runtime allocation)
__device__ float g_mx [N_NODES * CTOT];    // x @ W, node-major       (8 MB)
__device__ float g_mxw[N_NODES * CTOT];    // w[j,h] * mx[j,c]        (8 MB)
__device__ float g_wexp[N_NODES * NHEAD];  // exp(mx[n,h,:].a_dst[h]) (128 KB)

// ---------------- packed fp32x2 helpers ----------------
__device__ __forceinline__ void ffma2(unsigned long long& d,
                                      unsigned long long a,
                                      unsigned long long b) {
    asm("fma.rn.f32x2 %0, %1, %2, %0;" : "+l"(d) : "l"(a), "l"(b));
}
__device__ __forceinline__ unsigned long long pack_dup(float x) {
    unsigned long long r;
    unsigned u = __float_as_uint(x);
    asm("mov.b64 %0, {%1, %1};" : "=l"(r) : "r"(u));
    return r;
}
__device__ __forceinline__ float2 unpack2(unsigned long long v) {
    unsigned lo, hi;
    asm("mov.b64 {%0, %1}, %2;" : "=r"(lo), "=r"(hi) : "l"(v));
    return make_float2(__uint_as_float(lo), __uint_as_float(hi));
}

// ---------------------------------------------------------------------------
// Kernel 1: mx[n, h*64+d] = sum_f x[n,f] * W[h,f,d]
// 128x128 tile, BK=16, 256 threads, 8x8 per thread via packed f32x2 FMA.
// ---------------------------------------------------------------------------
#define BM 128
#define BN 128
#define BK 16

__global__ __launch_bounds__(256) void gemm_mx_kernel(
    const float* __restrict__ x, const float* __restrict__ W)
{
    __shared__ float As[BK][BM];   // A transposed: As[k][m]
    __shared__ float Bs[BK][BN];

    const int tid = threadIdx.x;
    const int tx  = tid & 15;      // output col group
    const int ty  = tid >> 4;      // output row group
    const int m0  = blockIdx.x * BM;
    const int c0  = blockIdx.y * BN;

    unsigned long long acc[8][4];  // acc[i][j2] = (acc[i][2j2], acc[i][2j2+1])
    #pragma unroll
    for (int i = 0; i < 8; i++)
        #pragma unroll
        for (int j = 0; j < 4; j++) acc[i][j] = 0ull;

    for (int f0 = 0; f0 < IN_F; f0 += BK) {
        #pragma unroll
        for (int l = 0; l < 2; l++) {
            int idx = tid + l * 256;
            int row = idx >> 2;
            int fc  = (idx & 3) * 4;
            float4 v = *(const float4*)(x + (size_t)(m0 + row) * IN_F + f0 + fc);
            As[fc + 0][row] = v.x;
            As[fc + 1][row] = v.y;
            As[fc + 2][row] = v.z;
            As[fc + 3][row] = v.w;
        }
        #pragma unroll
        for (int l = 0; l < 2; l++) {
            int idx = tid + l * 256;
            int k   = idx >> 5;
            int cc  = (idx & 31) * 4;
            int c   = c0 + cc;
            const float* wp = W + (size_t)(c >> 6) * (IN_F * DHEAD)
                                + (size_t)(f0 + k) * DHEAD + (c & 63);
            *(float4*)&Bs[k][cc] = *(const float4*)wp;
        }
        __syncthreads();

        #pragma unroll
        for (int k = 0; k < BK; k++) {
            float a[8];
            *(float4*)(a)     = *(float4*)&As[k][ty * 8];
            *(float4*)(a + 4) = *(float4*)&As[k][ty * 8 + 4];
            unsigned long long b2[4];
            {
                ulonglong2 t0 = *(const ulonglong2*)&Bs[k][tx * 8];
                ulonglong2 t1 = *(const ulonglong2*)&Bs[k][tx * 8 + 4];
                b2[0] = t0.x; b2[1] = t0.y; b2[2] = t1.x; b2[3] = t1.y;
            }
            #pragma unroll
            for (int i = 0; i < 8; i++) {
                unsigned long long aa = pack_dup(a[i]);
                #pragma unroll
                for (int j = 0; j < 4; j++) ffma2(acc[i][j], aa, b2[j]);
            }
        }
        __syncthreads();
    }

    #pragma unroll
    for (int i = 0; i < 8; i++) {
        int n = m0 + ty * 8 + i;
        float* op = g_mx + (size_t)n * CTOT + c0 + tx * 8;
        float2 p0 = unpack2(acc[i][0]), p1 = unpack2(acc[i][1]);
        float2 p2 = unpack2(acc[i][2]), p3 = unpack2(acc[i][3]);
        float4 o0 = make_float4(p0.x, p0.y, p1.x, p1.y);
        float4 o1 = make_float4(p2.x, p2.y, p3.x, p3.y);
        *(float4*)(op)     = o0;
        *(float4*)(op + 4) = o1;
    }
}

// ---------------------------------------------------------------------------
// Kernel 2: w[n,h] = exp(mx[n,h,:] . a_dst[h,:]);  mxw[n,c] = w[n, c/64]*mx[n,c]
// (the a_origin source term cancels inside the row softmax)
// One block per node, 8 warps = 8 heads for the dot, then scale pass.
// ---------------------------------------------------------------------------
__global__ __launch_bounds__(256) void wexp_scale_kernel(const float* __restrict__ a_dst)
{
    __shared__ float sh_w[NHEAD];
    const int n    = blockIdx.x;
    const int h    = threadIdx.x >> 5;
    const int lane = threadIdx.x & 31;
    const float* mrow = g_mx + (size_t)n * CTOT;

    const float* mp = mrow + h * DHEAD;
    const float* ap = a_dst + h * DHEAD;
    float t = mp[lane] * ap[lane] + mp[lane + 32] * ap[lane + 32];
    #pragma unroll
    for (int o = 16; o > 0; o >>= 1) t += __shfl_xor_sync(0xFFFFFFFFu, t, o);
    if (lane == 0) {
        float w = expf(t);
        sh_w[h] = w;
        g_wexp[n * NHEAD + h] = w;
    }
    __syncthreads();

    // scale: 256 threads x 2 channels each
    int c = threadIdx.x * 2;
    float w = sh_w[c >> 6];
    float2 v = *(const float2*)(mrow + c);
    float2 o = make_float2(v.x * w, v.y * w);
    *(float2*)(g_mxw + (size_t)n * CTOT + c) = o;
}

// ---------------------------------------------------------------------------
// Kernel 3: out[i,c] = (sum_{j in adj(i)} mxw[j,c]) / (sum_j w[j, c/64])
// One block (512 threads) per row.
//   Phase A: each of 16 warps compacts nonzeros of its 256-col slice (float4
//            loads + warp-scan, order preserved), then stages that slice's
//            weights w[j, 0..7] into shared.
//   Phase B: pure gather-ADD over neighbors, unrolled x4.
// ---------------------------------------------------------------------------
#define SEG_CAP 48

__global__ __launch_bounds__(512) void aggregate_kernel(
    const float* __restrict__ adj, float* __restrict__ out)
{
    __shared__ unsigned short seg[16][SEG_CAP];
    __shared__ float wsh[16][SEG_CAP][NHEAD];   // 24 KB
    __shared__ int cnts[16];

    const int i    = blockIdx.x;
    const int tid  = threadIdx.x;
    const int warp = tid >> 5;
    const int lane = tid & 31;

    // ---- Phase A: ordered compaction of this warp's 256-col slice ----
    {
        const float* arow = adj + (size_t)i * N_NODES + warp * 256;
        int cnt = 0;
        #pragma unroll
        for (int p = 0; p < 2; p++) {
            int col = p * 128 + lane * 4;
            float4 v = *(const float4*)(arow + col);
            unsigned m4 = (v.x > 0.f ? 1u : 0u) | (v.y > 0.f ? 2u : 0u)
                        | (v.z > 0.f ? 4u : 0u) | (v.w > 0.f ? 8u : 0u);
            int c = __popc(m4);
            // inclusive warp scan of c
            int inc = c;
            #pragma unroll
            for (int d = 1; d < 32; d <<= 1) {
                int t = __shfl_up_sync(0xFFFFFFFFu, inc, d);
                if (lane >= d) inc += t;
            }
            int pos = cnt + inc - c;     // exclusive offset
            int base = warp * 256 + col;
            #pragma unroll
            for (int b = 0; b < 4; b++)
                if ((m4 >> b) & 1u) seg[warp][pos++] = (unsigned short)(base + b);
            cnt += __shfl_sync(0xFFFFFFFFu, inc, 31);
        }
        __syncwarp();
        // stage weights for this slice's neighbors: wsh[warp][k][h] = w[seg[k], h]
        for (int idx = lane; idx < cnt * NHEAD; idx += 32) {
            int k = idx >> 3, h2 = idx & 7;
            wsh[warp][k][h2] = g_wexp[(int)seg[warp][k] * NHEAD + h2];
        }
        if (lane == 0) cnts[warp] = cnt;
    }
    __syncthreads();

    // ---- Phase B: gather-add. Thread tid owns channel tid, head tid/64. ----
    const int h = tid >> 6;
    float acc = 0.f, den = 0.f;
    #pragma unroll 1
    for (int w = 0; w < 16; w++) {
        const int nw = cnts[w];
        const unsigned short* s = seg[w];
        int k = 0;
        for (; k + 4 <= nw; k += 4) {
            int j0 = s[k], j1 = s[k+1], j2 = s[k+2], j3 = s[k+3];
            float m0 = __ldg(g_mxw + (size_t)j0 * CTOT + tid);
            float m1 = __ldg(g_mxw + (size_t)j1 * CTOT + tid);
            float m2 = __ldg(g_mxw + (size_t)j2 * CTOT + tid);
            float m3 = __ldg(g_mxw + (size_t)j3 * CTOT + tid);
            float w0 = wsh[w][k][h],   w1 = wsh[w][k+1][h];
            float w2 = wsh[w][k+2][h], w3 = wsh[w][k+3][h];
            acc += m0; acc += m1; acc += m2; acc += m3;
            den += w0; den += w1; den += w2; den += w3;
        }
        for (; k < nw; k++) {
            int j0 = s[k];
            acc += __ldg(g_mxw + (size_t)j0 * CTOT + tid);
            den += wsh[w][k][h];
        }
    }
    out[(size_t)i * CTOT + tid] = acc / den;
}

// ---------------------------------------------------------------------------
// Inputs: x[4096,512], adj[4096,4096], W[8,512,64], a_origin[8,64] (cancels),
//         a_dst[8,64].  Output: float32 [4096, 512]
// ---------------------------------------------------------------------------
extern "C" void kernel_launch(void* const* d_in, const int* in_sizes, int n_in,
                              void* d_out, int out_size)
{
    const float* x     = (const float*)d_in[0];
    const float* adj   = (const float*)d_in[1];
    const float* W     = (const float*)d_in[2];
    const float* a_dst = (const float*)d_in[4];
    float* out = (float*)d_out;

    dim3 ggrid(N_NODES / BM, CTOT / BN);   // (32, 4) = 128 blocks
    gemm_mx_kernel<<<ggrid, 256>>>(x, W);
    wexp_scale_kernel<<<N_NODES, 256>>>(a_dst);
    aggregate_kernel<<<N_NODES, 512>>>(adj, out);
}

// round 4
// speedup vs baseline: 1.1026x; 1.1026x over previous
#include <cuda_runtime.h>
#include <math.h>
#include <stdint.h>

#define N_NODES 4096
#define IN_F    512
#define NHEAD   8
#define DHEAD   64
#define CTOT    512

// Scratch (static device globals — no runtime allocation)
__device__ float g_mx  [N_NODES * CTOT];   // x @ W, node-major (8 MB, L2-resident)
__device__ float g_xt  [N_NODES * IN_F];   // x rounded to tf32 (8 MB)
__device__ float g_wt  [CTOT * IN_F];      // W^T K-major, tf32-rounded (1 MB)
__device__ float g_wexp[N_NODES * NHEAD];  // exp(mx[n,h,:].a_dst[h]) (128 KB)

// ---------------- helpers ----------------
__device__ __forceinline__ uint32_t smem_u32(const void* p) {
    return (uint32_t)__cvta_generic_to_shared(p);
}
__device__ __forceinline__ void cpa16(uint32_t saddr, const float* g) {
    asm volatile("cp.async.cg.shared.global [%0], [%1], 16;\n" :: "r"(saddr), "l"(g));
}
__device__ __forceinline__ float tf32r(float v) {
    uint32_t r;
    asm("cvt.rna.tf32.f32 %0, %1;" : "=r"(r) : "f"(v));
    return __uint_as_float(r);
}
__device__ __forceinline__ void mma_tf32(float* c, const uint32_t* a, const uint32_t* b) {
    asm volatile(
        "mma.sync.aligned.m16n8k8.row.col.f32.tf32.tf32.f32 "
        "{%0,%1,%2,%3}, {%4,%5,%6,%7}, {%8,%9}, {%0,%1,%2,%3};"
        : "+f"(c[0]), "+f"(c[1]), "+f"(c[2]), "+f"(c[3])
        : "r"(a[0]), "r"(a[1]), "r"(a[2]), "r"(a[3]), "r"(b[0]), "r"(b[1]));
}

// ---------------------------------------------------------------------------
// Prepass A: g_xt = round_tf32(x)
// ---------------------------------------------------------------------------
__global__ __launch_bounds__(256) void xt_kernel(const float* __restrict__ x)
{
    int i = (blockIdx.x * 256 + threadIdx.x) * 4;
    float4 v = __ldg((const float4*)(x + i));
    float4 o = make_float4(tf32r(v.x), tf32r(v.y), tf32r(v.z), tf32r(v.w));
    *(float4*)(g_xt + i) = o;
}

// ---------------------------------------------------------------------------
// Prepass B: g_wt[c][f] = round_tf32( W[c>>6][f][c&63] )   (64x64 transpose)
// ---------------------------------------------------------------------------
__global__ __launch_bounds__(256) void wt_kernel(const float* __restrict__ W)
{
    __shared__ float t[64][65];
    const int h  = blockIdx.x >> 3;
    const int f0 = (blockIdx.x & 7) * 64;
    const float* Wb = W + (size_t)h * IN_F * DHEAD + (size_t)f0 * DHEAD;
    for (int e = threadIdx.x; e < 4096; e += 256) {
        int i = e >> 6, d = e & 63;
        t[i][d] = Wb[i * 64 + d];
    }
    __syncthreads();
    for (int e = threadIdx.x; e < 4096; e += 256) {
        int d = e >> 6, i = e & 63;
        g_wt[(size_t)(h * 64 + d) * IN_F + f0 + i] = tf32r(t[i][d]);
    }
}

// ---------------------------------------------------------------------------
// Kernel 1: mx = xt @ wt^T via mma.sync m16n8k8 tf32 (portable PTX, HMMA).
// CTA tile 128x128, 8 warps of 64x32, K-tiles of 16, double-buffered cp.async.
// Smem rows padded to 20 floats -> conflict-free fragment LDS.
// ---------------------------------------------------------------------------
#define KT 16
#define NKT (IN_F / KT)   // 32

__global__ __launch_bounds__(256) void gemm_mx_kernel()
{
    __shared__ float As[2][128][20];
    __shared__ float Bs[2][128][20];

    const int tid  = threadIdx.x;
    const int wid  = tid >> 5, lane = tid & 31;
    const int wm   = wid >> 2, wn = wid & 3;        // 2 x 4 warp grid
    const int g    = lane >> 2, t4 = lane & 3;
    const int m0   = blockIdx.x * 128;
    const int c0   = blockIdx.y * 128;

    const uint32_t as_b = smem_u32(&As[0][0][0]);
    const uint32_t bs_b = smem_u32(&Bs[0][0][0]);

    float acc[4][4][4];
    #pragma unroll
    for (int mt = 0; mt < 4; mt++)
        #pragma unroll
        for (int nt = 0; nt < 4; nt++)
            #pragma unroll
            for (int q = 0; q < 4; q++) acc[mt][nt][q] = 0.f;

    const float* arow = g_xt + (size_t)m0 * IN_F;
    const float* brow = g_wt + (size_t)c0 * IN_F;

    auto fill = [&](int s, int t) {
        const int f0 = t * KT;
        #pragma unroll
        for (int l = 0; l < 2; l++) {
            int idx = tid + l * 256;
            int row = idx >> 2, kc = (idx & 3) * 4;
            uint32_t off = (uint32_t)(((s * 128 + row) * 20 + kc) * 4);
            cpa16(as_b + off, arow + (size_t)row * IN_F + f0 + kc);
            cpa16(bs_b + off, brow + (size_t)row * IN_F + f0 + kc);
        }
    };

    fill(0, 0);
    asm volatile("cp.async.commit_group;" ::: "memory");

    for (int t = 0; t < NKT; t++) {
        const int s = t & 1;
        if (t + 1 < NKT) {
            fill(s ^ 1, t + 1);
            asm volatile("cp.async.commit_group;" ::: "memory");
            asm volatile("cp.async.wait_group 1;" ::: "memory");
        } else {
            asm volatile("cp.async.wait_group 0;" ::: "memory");
        }
        __syncthreads();

        #pragma unroll
        for (int ks = 0; ks < 2; ks++) {
            const int kb = ks * 8;
            uint32_t af[4][4];
            #pragma unroll
            for (int mt = 0; mt < 4; mt++) {
                int m = wm * 64 + mt * 16 + g;
                af[mt][0] = __float_as_uint(As[s][m    ][kb + t4]);
                af[mt][1] = __float_as_uint(As[s][m + 8][kb + t4]);
                af[mt][2] = __float_as_uint(As[s][m    ][kb + t4 + 4]);
                af[mt][3] = __float_as_uint(As[s][m + 8][kb + t4 + 4]);
            }
            uint32_t bf[4][2];
            #pragma unroll
            for (int nt = 0; nt < 4; nt++) {
                int n = wn * 32 + nt * 8 + g;
                bf[nt][0] = __float_as_uint(Bs[s][n][kb + t4]);
                bf[nt][1] = __float_as_uint(Bs[s][n][kb + t4 + 4]);
            }
            #pragma unroll
            for (int mt = 0; mt < 4; mt++)
                #pragma unroll
                for (int nt = 0; nt < 4; nt++)
                    mma_tf32(acc[mt][nt], af[mt], bf[nt]);
        }
        __syncthreads();
    }

    // epilogue: c0q: (g, 2t4), c1: +1, c2: (g+8, 2t4), c3: +1
    #pragma unroll
    for (int mt = 0; mt < 4; mt++) {
        #pragma unroll
        for (int nt = 0; nt < 4; nt++) {
            int row = m0 + wm * 64 + mt * 16 + g;
            int col = c0 + wn * 32 + nt * 8 + t4 * 2;
            *(float2*)(g_mx + (size_t)row * CTOT + col) =
                make_float2(acc[mt][nt][0], acc[mt][nt][1]);
            *(float2*)(g_mx + (size_t)(row + 8) * CTOT + col) =
                make_float2(acc[mt][nt][2], acc[mt][nt][3]);
        }
    }
}

// ---------------------------------------------------------------------------
// Kernel 2: g_wexp[n,h] = exp(mx[n,h,:] . a_dst[h,:])
// (the a_origin source term is constant per row and cancels in the softmax)
// ---------------------------------------------------------------------------
__global__ __launch_bounds__(256) void wexp_kernel(const float* __restrict__ a_dst)
{
    const int n    = blockIdx.x;
    const int h    = threadIdx.x >> 5;
    const int lane = threadIdx.x & 31;
    const float* mp = g_mx + (size_t)n * CTOT + h * DHEAD;
    const float* ap = a_dst + h * DHEAD;
    float t = mp[lane] * ap[lane] + mp[lane + 32] * ap[lane + 32];
    #pragma unroll
    for (int o = 16; o > 0; o >>= 1) t += __shfl_xor_sync(0xFFFFFFFFu, t, o);
    if (lane == 0) g_wexp[n * NHEAD + h] = expf(t);
}

// ---------------------------------------------------------------------------
// Kernel 3: out[i,c] = sum_{j in adj(i)} w[j,h] mx[j,c] / sum_j w[j,h]
// One block (512 threads) per row. Phase A: ordered compaction to a unified
// neighbor list + weight staging. Phase B: 4 sub-streams x unroll-4 float4
// gathers (MLP=4/thread) + deterministic partial reduce.
// ---------------------------------------------------------------------------
#define NB_CAP 256

__global__ __launch_bounds__(512) void aggregate_kernel(
    const float* __restrict__ adj, float* __restrict__ out)
{
    __shared__ unsigned short seg[16][32];
    __shared__ int cnts[16], offs[16], nb_sh;
    __shared__ unsigned short ulist[NB_CAP];
    __shared__ float wsh[NB_CAP][NHEAD];
    __shared__ float4 pacc[4][128];
    __shared__ float  pden[4][128];

    const int i    = blockIdx.x;
    const int tid  = threadIdx.x;
    const int warp = tid >> 5;
    const int lane = tid & 31;

    // ---- Phase A ----
    {
        const float* arow = adj + (size_t)i * N_NODES + warp * 256;
        int cnt = 0;
        #pragma unroll
        for (int p = 0; p < 2; p++) {
            int col = p * 128 + lane * 4;
            float4 v = __ldg((const float4*)(arow + col));
            unsigned m4 = (v.x > 0.f ? 1u : 0u) | (v.y > 0.f ? 2u : 0u)
                        | (v.z > 0.f ? 4u : 0u) | (v.w > 0.f ? 8u : 0u);
            int c = __popc(m4), inc = c;
            #pragma unroll
            for (int d2 = 1; d2 < 32; d2 <<= 1) {
                int t = __shfl_up_sync(0xFFFFFFFFu, inc, d2);
                if (lane >= d2) inc += t;
            }
            int pos = cnt + inc - c;
            int base = warp * 256 + col;
            #pragma unroll
            for (int b = 0; b < 4; b++)
                if ((m4 >> b) & 1u) seg[warp][pos++] = (unsigned short)(base + b);
            cnt += __shfl_sync(0xFFFFFFFFu, inc, 31);
        }
        if (lane == 0) cnts[warp] = cnt;
    }
    __syncthreads();
    if (tid < 16) {
        int v = cnts[tid], s = v;
        #pragma unroll
        for (int d2 = 1; d2 < 16; d2 <<= 1) {
            int t = __shfl_up_sync(0x0000FFFFu, s, d2);
            if (tid >= d2) s += t;
        }
        offs[tid] = s - v;
        if (tid == 15) nb_sh = s;
    }
    __syncthreads();
    {
        const int o = offs[warp], cw = cnts[warp];
        for (int k = lane; k < cw; k += 32) ulist[o + k] = seg[warp][k];
        for (int idx = lane; idx < cw * NHEAD; idx += 32) {
            int k = idx >> 3, h2 = idx & 7;
            wsh[o + k][h2] = __ldg(g_wexp + (int)seg[warp][k] * NHEAD + h2);
        }
    }
    __syncthreads();

    // ---- Phase B ----
    const int nb  = nb_sh;
    const int cg  = tid & 127;    // float4 channel group
    const int sub = tid >> 7;     // 0..3
    const int h   = cg >> 4;
    float4 acc = make_float4(0.f, 0.f, 0.f, 0.f);
    float  den = 0.f;
    int k = sub;
    for (; k + 12 < nb; k += 16) {
        int j0 = ulist[k], j1 = ulist[k + 4], j2 = ulist[k + 8], j3 = ulist[k + 12];
        float4 a0 = __ldg((const float4*)(g_mx + (size_t)j0 * CTOT + cg * 4));
        float4 a1 = __ldg((const float4*)(g_mx + (size_t)j1 * CTOT + cg * 4));
        float4 a2 = __ldg((const float4*)(g_mx + (size_t)j2 * CTOT + cg * 4));
        float4 a3 = __ldg((const float4*)(g_mx + (size_t)j3 * CTOT + cg * 4));
        float w0 = wsh[k][h], w1 = wsh[k + 4][h], w2 = wsh[k + 8][h], w3 = wsh[k + 12][h];
        acc.x += a0.x * w0; acc.y += a0.y * w0; acc.z += a0.z * w0; acc.w += a0.w * w0;
        acc.x += a1.x * w1; acc.y += a1.y * w1; acc.z += a1.z * w1; acc.w += a1.w * w1;
        acc.x += a2.x * w2; acc.y += a2.y * w2; acc.z += a2.z * w2; acc.w += a2.w * w2;
        acc.x += a3.x * w3; acc.y += a3.y * w3; acc.z += a3.z * w3; acc.w += a3.w * w3;
        den += w0; den += w1; den += w2; den += w3;
    }
    for (; k < nb; k += 4) {
        int j0 = ulist[k];
        float4 a0 = __ldg((const float4*)(g_mx + (size_t)j0 * CTOT + cg * 4));
        float w0 = wsh[k][h];
        acc.x += a0.x * w0; acc.y += a0.y * w0; acc.z += a0.z * w0; acc.w += a0.w * w0;
        den += w0;
    }
    pacc[sub][cg] = acc;
    pden[sub][cg] = den;
    __syncthreads();

    if (tid < 128) {
        float4 r = pacc[0][tid]; float dd = pden[0][tid];
        #pragma unroll
        for (int s2 = 1; s2 < 4; s2++) {
            float4 q = pacc[s2][tid];
            r.x += q.x; r.y += q.y; r.z += q.z; r.w += q.w;
            dd += pden[s2][tid];
        }
        float inv = 1.f / dd;
        *(float4*)(out + (size_t)i * CTOT + tid * 4) =
            make_float4(r.x * inv, r.y * inv, r.z * inv, r.w * inv);
    }
}

// ---------------------------------------------------------------------------
// Inputs: x[4096,512], adj[4096,4096], W[8,512,64], a_origin[8,64] (cancels),
//         a_dst[8,64].  Output: float32 [4096, 512]
// ---------------------------------------------------------------------------
extern "C" void kernel_launch(void* const* d_in, const int* in_sizes, int n_in,
                              void* d_out, int out_size)
{
    const float* x     = (const float*)d_in[0];
    const float* adj   = (const float*)d_in[1];
    const float* W     = (const float*)d_in[2];
    const float* a_dst = (const float*)d_in[4];
    float* out = (float*)d_out;

    xt_kernel<<<N_NODES * IN_F / (256 * 4), 256>>>(x);
    wt_kernel<<<64, 256>>>(W);
    gemm_mx_kernel<<<dim3(32, 4), 256>>>();
    wexp_kernel<<<N_NODES, 256>>>(a_dst);
    aggregate_kernel<<<N_NODES, 512>>>(adj, out);
}

// round 5
// speedup vs baseline: 2.0860x; 1.8918x over previous
#include <cuda_runtime.h>
#include <math.h>
#include <stdint.h>

#define N_NODES 4096
#define IN_F    512
#define NHEAD   8
#define DHEAD   64
#define CTOT    512

// Scratch (static device globals — no runtime allocation)
__device__ float g_mx  [N_NODES * CTOT];   // x @ W, node-major (8 MB, L2-resident)
__device__ float g_xt  [N_NODES * IN_F];   // x rounded to tf32 (8 MB)
__device__ float g_wt  [CTOT * IN_F];      // W^T K-major, tf32-rounded (1 MB)
__device__ float g_wexp[N_NODES * NHEAD];  // exp(mx[n,h,:].a_dst[h]) (128 KB)

// ---------------- helpers ----------------
__device__ __forceinline__ uint32_t smem_u32(const void* p) {
    return (uint32_t)__cvta_generic_to_shared(p);
}
__device__ __forceinline__ void cpa16(uint32_t saddr, const float* g) {
    asm volatile("cp.async.cg.shared.global [%0], [%1], 16;\n" :: "r"(saddr), "l"(g));
}
__device__ __forceinline__ float tf32r(float v) {
    uint32_t r;
    asm("cvt.rna.tf32.f32 %0, %1;" : "=r"(r) : "f"(v));
    return __uint_as_float(r);
}
__device__ __forceinline__ void mma_tf32(float* c, const uint32_t* a, const uint32_t* b) {
    asm volatile(
        "mma.sync.aligned.m16n8k8.row.col.f32.tf32.tf32.f32 "
        "{%0,%1,%2,%3}, {%4,%5,%6,%7}, {%8,%9}, {%0,%1,%2,%3};"
        : "+f"(c[0]), "+f"(c[1]), "+f"(c[2]), "+f"(c[3])
        : "r"(a[0]), "r"(a[1]), "r"(a[2]), "r"(a[3]), "r"(b[0]), "r"(b[1]));
}

// ---------------------------------------------------------------------------
// Prep (fused): blocks [0,2048): g_xt = tf32(x);  blocks [2048,2112): g_wt
// ---------------------------------------------------------------------------
__global__ __launch_bounds__(256) void prep_kernel(const float* __restrict__ x,
                                                   const float* __restrict__ W)
{
    if (blockIdx.x < 2048) {
        int i = (blockIdx.x * 256 + threadIdx.x) * 4;
        float4 v = __ldg((const float4*)(x + i));
        *(float4*)(g_xt + i) = make_float4(tf32r(v.x), tf32r(v.y), tf32r(v.z), tf32r(v.w));
    } else {
        __shared__ float t[64][65];
        const int b  = blockIdx.x - 2048;
        const int h  = b >> 3;
        const int f0 = (b & 7) * 64;
        const float* Wb = W + (size_t)h * IN_F * DHEAD + (size_t)f0 * DHEAD;
        for (int e = threadIdx.x; e < 4096; e += 256) {
            int i = e >> 6, d = e & 63;
            t[i][d] = Wb[i * 64 + d];
        }
        __syncthreads();
        for (int e = threadIdx.x; e < 4096; e += 256) {
            int d = e >> 6, i = e & 63;
            g_wt[(size_t)(h * 64 + d) * IN_F + f0 + i] = tf32r(t[i][d]);
        }
    }
}

// ---------------------------------------------------------------------------
// Kernel 1: mx = xt @ wt^T via mma.sync m16n8k8 tf32 (unchanged from R4).
// ---------------------------------------------------------------------------
#define KT 16
#define NKT (IN_F / KT)   // 32

__global__ __launch_bounds__(256) void gemm_mx_kernel()
{
    __shared__ float As[2][128][20];
    __shared__ float Bs[2][128][20];

    const int tid  = threadIdx.x;
    const int wid  = tid >> 5, lane = tid & 31;
    const int wm   = wid >> 2, wn = wid & 3;
    const int g    = lane >> 2, t4 = lane & 3;
    const int m0   = blockIdx.x * 128;
    const int c0   = blockIdx.y * 128;

    const uint32_t as_b = smem_u32(&As[0][0][0]);
    const uint32_t bs_b = smem_u32(&Bs[0][0][0]);

    float acc[4][4][4];
    #pragma unroll
    for (int mt = 0; mt < 4; mt++)
        #pragma unroll
        for (int nt = 0; nt < 4; nt++)
            #pragma unroll
            for (int q = 0; q < 4; q++) acc[mt][nt][q] = 0.f;

    const float* arow = g_xt + (size_t)m0 * IN_F;
    const float* brow = g_wt + (size_t)c0 * IN_F;

    auto fill = [&](int s, int t) {
        const int f0 = t * KT;
        #pragma unroll
        for (int l = 0; l < 2; l++) {
            int idx = tid + l * 256;
            int row = idx >> 2, kc = (idx & 3) * 4;
            uint32_t off = (uint32_t)(((s * 128 + row) * 20 + kc) * 4);
            cpa16(as_b + off, arow + (size_t)row * IN_F + f0 + kc);
            cpa16(bs_b + off, brow + (size_t)row * IN_F + f0 + kc);
        }
    };

    fill(0, 0);
    asm volatile("cp.async.commit_group;" ::: "memory");

    for (int t = 0; t < NKT; t++) {
        const int s = t & 1;
        if (t + 1 < NKT) {
            fill(s ^ 1, t + 1);
            asm volatile("cp.async.commit_group;" ::: "memory");
            asm volatile("cp.async.wait_group 1;" ::: "memory");
        } else {
            asm volatile("cp.async.wait_group 0;" ::: "memory");
        }
        __syncthreads();

        #pragma unroll
        for (int ks = 0; ks < 2; ks++) {
            const int kb = ks * 8;
            uint32_t af[4][4];
            #pragma unroll
            for (int mt = 0; mt < 4; mt++) {
                int m = wm * 64 + mt * 16 + g;
                af[mt][0] = __float_as_uint(As[s][m    ][kb + t4]);
                af[mt][1] = __float_as_uint(As[s][m + 8][kb + t4]);
                af[mt][2] = __float_as_uint(As[s][m    ][kb + t4 + 4]);
                af[mt][3] = __float_as_uint(As[s][m + 8][kb + t4 + 4]);
            }
            uint32_t bf[4][2];
            #pragma unroll
            for (int nt = 0; nt < 4; nt++) {
                int n = wn * 32 + nt * 8 + g;
                bf[nt][0] = __float_as_uint(Bs[s][n][kb + t4]);
                bf[nt][1] = __float_as_uint(Bs[s][n][kb + t4 + 4]);
            }
            #pragma unroll
            for (int mt = 0; mt < 4; mt++)
                #pragma unroll
                for (int nt = 0; nt < 4; nt++)
                    mma_tf32(acc[mt][nt], af[mt], bf[nt]);
        }
        __syncthreads();
    }

    #pragma unroll
    for (int mt = 0; mt < 4; mt++) {
        #pragma unroll
        for (int nt = 0; nt < 4; nt++) {
            int row = m0 + wm * 64 + mt * 16 + g;
            int col = c0 + wn * 32 + nt * 8 + t4 * 2;
            *(float2*)(g_mx + (size_t)row * CTOT + col) =
                make_float2(acc[mt][nt][0], acc[mt][nt][1]);
            *(float2*)(g_mx + (size_t)(row + 8) * CTOT + col) =
                make_float2(acc[mt][nt][2], acc[mt][nt][3]);
        }
    }
}

// ---------------------------------------------------------------------------
// Kernel 2: g_wexp[n,h] = exp(mx[n,h,:] . a_dst[h,:])
// (a_origin source term cancels in the row softmax)
// One warp = one (node, head-pair): float4 per lane, half-warp reduce.
// ---------------------------------------------------------------------------
__global__ __launch_bounds__(256) void wexp_kernel(const float* __restrict__ a_dst)
{
    const int gw   = blockIdx.x * 8 + (threadIdx.x >> 5);   // global warp
    const int lane = threadIdx.x & 31;
    const int n    = gw >> 2;
    const int hp   = gw & 3;                                // heads 2hp, 2hp+1
    const int head = 2 * hp + (lane >> 4);

    float4 v = __ldg((const float4*)(g_mx + (size_t)n * CTOT + hp * 128 + lane * 4));
    float4 a = __ldg((const float4*)(a_dst + head * DHEAD + (lane & 15) * 4));
    float t = v.x * a.x + v.y * a.y + v.z * a.z + v.w * a.w;
    #pragma unroll
    for (int o = 8; o > 0; o >>= 1) t += __shfl_xor_sync(0xFFFFFFFFu, t, o);
    if ((lane & 15) == 0) g_wexp[n * NHEAD + head] = expf(t);
}

// ---------------------------------------------------------------------------
// Kernel 3: out[i,c] = sum_{j in adj(i)} w[j,h] mx[j,c] / sum_j w[j,h]
// 128 threads/block, one block per row -> ~12 resident blocks/SM for latency
// hiding. Phase A: 4 warps compact 1024-col slices (ordered). Phase B: each
// thread owns one float4 channel group, unroll-4 gather over neighbors.
// ---------------------------------------------------------------------------
#define NB_CAP  256
#define SEG_CAP 96

__global__ __launch_bounds__(128) void aggregate_kernel(
    const float* __restrict__ adj, float* __restrict__ out)
{
    __shared__ unsigned short seg[4][SEG_CAP];
    __shared__ int cnts[4], nb_sh;
    __shared__ int offs[4];
    __shared__ unsigned short ulist[NB_CAP];
    __shared__ float wsh[NB_CAP][NHEAD];

    const int i    = blockIdx.x;
    const int tid  = threadIdx.x;
    const int warp = tid >> 5;
    const int lane = tid & 31;

    // ---- Phase A: ordered compaction, warp w covers cols [w*1024,(w+1)*1024) ----
    {
        const float* arow = adj + (size_t)i * N_NODES + warp * 1024;
        int cnt = 0;
        #pragma unroll
        for (int p = 0; p < 8; p++) {
            int col = p * 128 + lane * 4;
            float4 v = __ldg((const float4*)(arow + col));
            unsigned m4 = (v.x > 0.f ? 1u : 0u) | (v.y > 0.f ? 2u : 0u)
                        | (v.z > 0.f ? 4u : 0u) | (v.w > 0.f ? 8u : 0u);
            int c = __popc(m4), inc = c;
            #pragma unroll
            for (int d2 = 1; d2 < 32; d2 <<= 1) {
                int t = __shfl_up_sync(0xFFFFFFFFu, inc, d2);
                if (lane >= d2) inc += t;
            }
            int pos = cnt + inc - c;
            int base = warp * 1024 + col;
            #pragma unroll
            for (int b = 0; b < 4; b++)
                if ((m4 >> b) & 1u) seg[warp][pos++] = (unsigned short)(base + b);
            cnt += __shfl_sync(0xFFFFFFFFu, inc, 31);
        }
        if (lane == 0) cnts[warp] = cnt;
    }
    __syncthreads();
    if (tid == 0) {
        int s = 0;
        #pragma unroll
        for (int w = 0; w < 4; w++) { offs[w] = s; s += cnts[w]; }
        nb_sh = s;
    }
    __syncthreads();
    {
        const int o = offs[warp], cw = cnts[warp];
        for (int k = lane; k < cw; k += 32) ulist[o + k] = seg[warp][k];
        for (int idx = lane; idx < cw * NHEAD; idx += 32) {
            int k = idx >> 3, h2 = idx & 7;
            wsh[o + k][h2] = __ldg(g_wexp + (int)seg[warp][k] * NHEAD + h2);
        }
    }
    __syncthreads();

    // ---- Phase B: thread tid owns channels [tid*4, tid*4+4), head tid/16 ----
    const int nb = nb_sh;
    const int h  = tid >> 4;
    const float* mxb = g_mx + (size_t)tid * 4;
    float4 acc = make_float4(0.f, 0.f, 0.f, 0.f);
    float  den = 0.f;
    int k = 0;
    for (; k + 4 <= nb; k += 4) {
        int j0 = ulist[k], j1 = ulist[k + 1], j2 = ulist[k + 2], j3 = ulist[k + 3];
        float4 a0 = __ldg((const float4*)(mxb + (size_t)j0 * CTOT));
        float4 a1 = __ldg((const float4*)(mxb + (size_t)j1 * CTOT));
        float4 a2 = __ldg((const float4*)(mxb + (size_t)j2 * CTOT));
        float4 a3 = __ldg((const float4*)(mxb + (size_t)j3 * CTOT));
        float w0 = wsh[k][h], w1 = wsh[k + 1][h], w2 = wsh[k + 2][h], w3 = wsh[k + 3][h];
        acc.x += a0.x * w0; acc.y += a0.y * w0; acc.z += a0.z * w0; acc.w += a0.w * w0;
        acc.x += a1.x * w1; acc.y += a1.y * w1; acc.z += a1.z * w1; acc.w += a1.w * w1;
        acc.x += a2.x * w2; acc.y += a2.y * w2; acc.z += a2.z * w2; acc.w += a2.w * w2;
        acc.x += a3.x * w3; acc.y += a3.y * w3; acc.z += a3.z * w3; acc.w += a3.w * w3;
        den += w0; den += w1; den += w2; den += w3;
    }
    for (; k < nb; k++) {
        int j0 = ulist[k];
        float4 a0 = __ldg((const float4*)(mxb + (size_t)j0 * CTOT));
        float w0 = wsh[k][h];
        acc.x += a0.x * w0; acc.y += a0.y * w0; acc.z += a0.z * w0; acc.w += a0.w * w0;
        den += w0;
    }
    float inv = 1.f / den;
    *(float4*)(out + (size_t)i * CTOT + tid * 4) =
        make_float4(acc.x * inv, acc.y * inv, acc.z * inv, acc.w * inv);
}

// ---------------------------------------------------------------------------
// Inputs: x[4096,512], adj[4096,4096], W[8,512,64], a_origin[8,64] (cancels),
//         a_dst[8,64].  Output: float32 [4096, 512]
// ---------------------------------------------------------------------------
extern "C" void kernel_launch(void* const* d_in, const int* in_sizes, int n_in,
                              void* d_out, int out_size)
{
    const float* x     = (const float*)d_in[0];
    const float* adj   = (const float*)d_in[1];
    const float* W     = (const float*)d_in[2];
    const float* a_dst = (const float*)d_in[4];
    float* out = (float*)d_out;

    prep_kernel<<<2112, 256>>>(x, W);
    gemm_mx_kernel<<<dim3(32, 4), 256>>>();
    wexp_kernel<<<2048, 256>>>(a_dst);
    aggregate_kernel<<<N_NODES, 128>>>(adj, out);
}

// round 6
// speedup vs baseline: 2.3891x; 1.1453x over previous
#include <cuda_runtime.h>
#include <cuda_fp16.h>
#include <math.h>
#include <stdint.h>

#define N_NODES 4096
#define IN_F    512
#define NHEAD   8
#define DHEAD   64
#define CTOT    512

// Scratch (static device globals — no runtime allocation)
__device__ __half g_mxh[N_NODES * CTOT];   // x @ W in fp16 (4 MB, L2-resident)
__device__ float  g_wt [CTOT * IN_F];      // W^T K-major, tf32-rounded (1 MB)
__device__ float  g_wexp[N_NODES * NHEAD]; // exp(mx[n,h,:].a_dst[h]) (128 KB)

// ---------------- helpers ----------------
__device__ __forceinline__ uint32_t smem_u32(const void* p) {
    return (uint32_t)__cvta_generic_to_shared(p);
}
__device__ __forceinline__ void cpa16(uint32_t saddr, const float* g) {
    asm volatile("cp.async.cg.shared.global [%0], [%1], 16;\n" :: "r"(saddr), "l"(g));
}
__device__ __forceinline__ float tf32r(float v) {
    uint32_t r;
    asm("cvt.rna.tf32.f32 %0, %1;" : "=r"(r) : "f"(v));
    return __uint_as_float(r);
}
__device__ __forceinline__ void mma_tf32(float* c, const uint32_t* a, const uint32_t* b) {
    asm volatile(
        "mma.sync.aligned.m16n8k8.row.col.f32.tf32.tf32.f32 "
        "{%0,%1,%2,%3}, {%4,%5,%6,%7}, {%8,%9}, {%0,%1,%2,%3};"
        : "+f"(c[0]), "+f"(c[1]), "+f"(c[2]), "+f"(c[3])
        : "r"(a[0]), "r"(a[1]), "r"(a[2]), "r"(a[3]), "r"(b[0]), "r"(b[1]));
}

// ---------------------------------------------------------------------------
// Prep: g_wt[c][f] = round_tf32(W[c>>6][f][c&63])  (64x64 transpose, 64 blocks)
// ---------------------------------------------------------------------------
__global__ __launch_bounds__(256) void prep_kernel(const float* __restrict__ W)
{
    __shared__ float t[64][65];
    const int h  = blockIdx.x >> 3;
    const int f0 = (blockIdx.x & 7) * 64;
    const float* Wb = W + (size_t)h * IN_F * DHEAD + (size_t)f0 * DHEAD;
    for (int e = threadIdx.x; e < 4096; e += 256) {
        int i = e >> 6, d = e & 63;
        t[i][d] = Wb[i * 64 + d];
    }
    __syncthreads();
    for (int e = threadIdx.x; e < 4096; e += 256) {
        int d = e >> 6, i = e & 63;
        g_wt[(size_t)(h * 64 + d) * IN_F + f0 + i] = tf32r(t[i][d]);
    }
}

// ---------------------------------------------------------------------------
// Kernel 1: mx = x @ wt^T via mma.sync m16n8k8 tf32.
// A side reads x directly (implicit tf32 truncation in HW — statistically
// equivalent to rounding here since b_k signs are random).
// Epilogue writes fp16 g_mxh.
// ---------------------------------------------------------------------------
#define KT 16
#define NKT (IN_F / KT)   // 32

__global__ __launch_bounds__(256) void gemm_mx_kernel(const float* __restrict__ x)
{
    __shared__ float As[2][128][20];
    __shared__ float Bs[2][128][20];

    const int tid  = threadIdx.x;
    const int wid  = tid >> 5, lane = tid & 31;
    const int wm   = wid >> 2, wn = wid & 3;
    const int g    = lane >> 2, t4 = lane & 3;
    const int m0   = blockIdx.x * 128;
    const int c0   = blockIdx.y * 128;

    const uint32_t as_b = smem_u32(&As[0][0][0]);
    const uint32_t bs_b = smem_u32(&Bs[0][0][0]);

    float acc[4][4][4];
    #pragma unroll
    for (int mt = 0; mt < 4; mt++)
        #pragma unroll
        for (int nt = 0; nt < 4; nt++)
            #pragma unroll
            for (int q = 0; q < 4; q++) acc[mt][nt][q] = 0.f;

    const float* arow = x    + (size_t)m0 * IN_F;
    const float* brow = g_wt + (size_t)c0 * IN_F;

    auto fill = [&](int s, int t) {
        const int f0 = t * KT;
        #pragma unroll
        for (int l = 0; l < 2; l++) {
            int idx = tid + l * 256;
            int row = idx >> 2, kc = (idx & 3) * 4;
            uint32_t off = (uint32_t)(((s * 128 + row) * 20 + kc) * 4);
            cpa16(as_b + off, arow + (size_t)row * IN_F + f0 + kc);
            cpa16(bs_b + off, brow + (size_t)row * IN_F + f0 + kc);
        }
    };

    fill(0, 0);
    asm volatile("cp.async.commit_group;" ::: "memory");

    for (int t = 0; t < NKT; t++) {
        const int s = t & 1;
        if (t + 1 < NKT) {
            fill(s ^ 1, t + 1);
            asm volatile("cp.async.commit_group;" ::: "memory");
            asm volatile("cp.async.wait_group 1;" ::: "memory");
        } else {
            asm volatile("cp.async.wait_group 0;" ::: "memory");
        }
        __syncthreads();

        #pragma unroll
        for (int ks = 0; ks < 2; ks++) {
            const int kb = ks * 8;
            uint32_t af[4][4];
            #pragma unroll
            for (int mt = 0; mt < 4; mt++) {
                int m = wm * 64 + mt * 16 + g;
                af[mt][0] = __float_as_uint(As[s][m    ][kb + t4]);
                af[mt][1] = __float_as_uint(As[s][m + 8][kb + t4]);
                af[mt][2] = __float_as_uint(As[s][m    ][kb + t4 + 4]);
                af[mt][3] = __float_as_uint(As[s][m + 8][kb + t4 + 4]);
            }
            uint32_t bf[4][2];
            #pragma unroll
            for (int nt = 0; nt < 4; nt++) {
                int n = wn * 32 + nt * 8 + g;
                bf[nt][0] = __float_as_uint(Bs[s][n][kb + t4]);
                bf[nt][1] = __float_as_uint(Bs[s][n][kb + t4 + 4]);
            }
            #pragma unroll
            for (int mt = 0; mt < 4; mt++)
                #pragma unroll
                for (int nt = 0; nt < 4; nt++)
                    mma_tf32(acc[mt][nt], af[mt], bf[nt]);
        }
        __syncthreads();
    }

    // epilogue: write fp16
    #pragma unroll
    for (int mt = 0; mt < 4; mt++) {
        #pragma unroll
        for (int nt = 0; nt < 4; nt++) {
            int row = m0 + wm * 64 + mt * 16 + g;
            int col = c0 + wn * 32 + nt * 8 + t4 * 2;
            *(__half2*)(g_mxh + (size_t)row * CTOT + col) =
                __floats2half2_rn(acc[mt][nt][0], acc[mt][nt][1]);
            *(__half2*)(g_mxh + (size_t)(row + 8) * CTOT + col) =
                __floats2half2_rn(acc[mt][nt][2], acc[mt][nt][3]);
        }
    }
}

// ---------------------------------------------------------------------------
// Kernel 2: g_wexp[n,h] = exp(mx[n,h,:] . a_dst[h,:])
// (a_origin source term cancels in the row softmax)
// One warp = one (node, head-pair): 4 halves per lane, 16-lane reduce.
// ---------------------------------------------------------------------------
__global__ __launch_bounds__(256) void wexp_kernel(const float* __restrict__ a_dst)
{
    const int gw   = blockIdx.x * 8 + (threadIdx.x >> 5);   // global warp
    const int lane = threadIdx.x & 31;
    const int n    = gw >> 2;
    const int hp   = gw & 3;                                // heads 2hp, 2hp+1
    const int head = 2 * hp + (lane >> 4);

    uint2 raw = __ldg((const uint2*)(g_mxh + (size_t)n * CTOT + hp * 128 + lane * 4));
    float2 v0 = __half22float2(*(__half2*)&raw.x);
    float2 v1 = __half22float2(*(__half2*)&raw.y);
    float4 a  = __ldg((const float4*)(a_dst + head * DHEAD + (lane & 15) * 4));
    float t = v0.x * a.x + v0.y * a.y + v1.x * a.z + v1.y * a.w;
    #pragma unroll
    for (int o = 8; o > 0; o >>= 1) t += __shfl_xor_sync(0xFFFFFFFFu, t, o);
    if ((lane & 15) == 0) g_wexp[n * NHEAD + head] = expf(t);
}

// ---------------------------------------------------------------------------
// Kernel 3: out[i,c] = sum_{j in adj(i)} w[j,h] mx[j,c] / sum_j w[j,h]
// 128 threads/block, one block per row. Phase A: ordered compaction.
// Phase B: 64 channel-groups (8 halves each) x 2 neighbor sub-streams,
// unroll-4 uint4 gathers, fp32 accumulation, deterministic reduce.
// ---------------------------------------------------------------------------
#define NB_CAP  256
#define SEG_CAP 96

__device__ __forceinline__ void acc8(float* acc, uint4 r, float w) {
    float2 f0 = __half22float2(*(__half2*)&r.x);
    float2 f1 = __half22float2(*(__half2*)&r.y);
    float2 f2 = __half22float2(*(__half2*)&r.z);
    float2 f3 = __half22float2(*(__half2*)&r.w);
    acc[0] += f0.x * w; acc[1] += f0.y * w;
    acc[2] += f1.x * w; acc[3] += f1.y * w;
    acc[4] += f2.x * w; acc[5] += f2.y * w;
    acc[6] += f3.x * w; acc[7] += f3.y * w;
}

__global__ __launch_bounds__(128) void aggregate_kernel(
    const float* __restrict__ adj, float* __restrict__ out)
{
    __shared__ unsigned short seg[4][SEG_CAP];
    __shared__ int cnts[4], nb_sh;
    __shared__ int offs[4];
    __shared__ unsigned short ulist[NB_CAP];
    __shared__ float wsh[NB_CAP][NHEAD];
    __shared__ float pac[64][9];
    __shared__ float pden1[64];

    const int i    = blockIdx.x;
    const int tid  = threadIdx.x;
    const int warp = tid >> 5;
    const int lane = tid & 31;

    // ---- Phase A: ordered compaction, warp w covers cols [w*1024,(w+1)*1024) ----
    {
        const float* arow = adj + (size_t)i * N_NODES + warp * 1024;
        int cnt = 0;
        #pragma unroll
        for (int p = 0; p < 8; p++) {
            int col = p * 128 + lane * 4;
            float4 v = __ldg((const float4*)(arow + col));
            unsigned m4 = (v.x > 0.f ? 1u : 0u) | (v.y > 0.f ? 2u : 0u)
                        | (v.z > 0.f ? 4u : 0u) | (v.w > 0.f ? 8u : 0u);
            int c = __popc(m4), inc = c;
            #pragma unroll
            for (int d2 = 1; d2 < 32; d2 <<= 1) {
                int t = __shfl_up_sync(0xFFFFFFFFu, inc, d2);
                if (lane >= d2) inc += t;
            }
            int pos = cnt + inc - c;
            int base = warp * 1024 + col;
            #pragma unroll
            for (int b = 0; b < 4; b++)
                if ((m4 >> b) & 1u) seg[warp][pos++] = (unsigned short)(base + b);
            cnt += __shfl_sync(0xFFFFFFFFu, inc, 31);
        }
        if (lane == 0) cnts[warp] = cnt;
    }
    __syncthreads();
    if (tid == 0) {
        int s = 0;
        #pragma unroll
        for (int w = 0; w < 4; w++) { offs[w] = s; s += cnts[w]; }
        nb_sh = s;
    }
    __syncthreads();
    {
        const int o = offs[warp], cw = cnts[warp];
        for (int k = lane; k < cw; k += 32) ulist[o + k] = seg[warp][k];
        for (int idx = lane; idx < cw * NHEAD; idx += 32) {
            int k = idx >> 3, h2 = idx & 7;
            wsh[o + k][h2] = __ldg(g_wexp + (int)seg[warp][k] * NHEAD + h2);
        }
    }
    __syncthreads();

    // ---- Phase B ----
    const int nb  = nb_sh;
    const int cg  = tid & 63;            // channels [cg*8, cg*8+8)
    const int sub = tid >> 6;            // 0/1, neighbors k === sub (mod 2)
    const int h   = cg >> 3;
    const __half* base = g_mxh + cg * 8;

    float acc[8] = {0.f, 0.f, 0.f, 0.f, 0.f, 0.f, 0.f, 0.f};
    float den = 0.f;
    int k = sub;
    for (; k + 6 < nb; k += 8) {
        int j0 = ulist[k], j1 = ulist[k + 2], j2 = ulist[k + 4], j3 = ulist[k + 6];
        uint4 r0 = __ldg((const uint4*)(base + (size_t)j0 * CTOT));
        uint4 r1 = __ldg((const uint4*)(base + (size_t)j1 * CTOT));
        uint4 r2 = __ldg((const uint4*)(base + (size_t)j2 * CTOT));
        uint4 r3 = __ldg((const uint4*)(base + (size_t)j3 * CTOT));
        float w0 = wsh[k][h], w1 = wsh[k + 2][h], w2 = wsh[k + 4][h], w3 = wsh[k + 6][h];
        acc8(acc, r0, w0); acc8(acc, r1, w1); acc8(acc, r2, w2); acc8(acc, r3, w3);
        den += w0; den += w1; den += w2; den += w3;
    }
    for (; k < nb; k += 2) {
        int j0 = ulist[k];
        uint4 r0 = __ldg((const uint4*)(base + (size_t)j0 * CTOT));
        float w0 = wsh[k][h];
        acc8(acc, r0, w0);
        den += w0;
    }

    if (sub == 1) {
        #pragma unroll
        for (int q = 0; q < 8; q++) pac[cg][q] = acc[q];
        pden1[cg] = den;
    }
    __syncthreads();
    if (sub == 0) {
        den += pden1[cg];
        float inv = 1.f / den;
        float* op = out + (size_t)i * CTOT + cg * 8;
        *(float4*)(op) = make_float4((acc[0] + pac[cg][0]) * inv,
                                     (acc[1] + pac[cg][1]) * inv,
                                     (acc[2] + pac[cg][2]) * inv,
                                     (acc[3] + pac[cg][3]) * inv);
        *(float4*)(op + 4) = make_float4((acc[4] + pac[cg][4]) * inv,
                                         (acc[5] + pac[cg][5]) * inv,
                                         (acc[6] + pac[cg][6]) * inv,
                                         (acc[7] + pac[cg][7]) * inv);
    }
}

// ---------------------------------------------------------------------------
// Inputs: x[4096,512], adj[4096,4096], W[8,512,64], a_origin[8,64] (cancels),
//         a_dst[8,64].  Output: float32 [4096, 512]
// ---------------------------------------------------------------------------
extern "C" void kernel_launch(void* const* d_in, const int* in_sizes, int n_in,
                              void* d_out, int out_size)
{
    const float* x     = (const float*)d_in[0];
    const float* adj   = (const float*)d_in[1];
    const float* W     = (const float*)d_in[2];
    const float* a_dst = (const float*)d_in[4];
    float* out = (float*)d_out;

    prep_kernel<<<64, 256>>>(W);
    gemm_mx_kernel<<<dim3(32, 4), 256>>>(x);
    wexp_kernel<<<2048, 256>>>(a_dst);
    aggregate_kernel<<<N_NODES, 128>>>(adj, out);
}